// round 13
// baseline (speedup 1.0000x reference)
#include <cuda_runtime.h>
#include <cuda_bf16.h>
#include <math.h>
#include <stdint.h>

// ---------------------------------------------------------------------------
// BaseCrossAttention fused pipeline.
// R2-exact structure (proven 495.6us) + __launch_bounds__(256,2) on the GEMM
// to pin 2 CTAs/SM (occupancy hypothesis test).
// B=32, T=1024, N=77, D=512, TD=256, TE=2048, H=8, dh=64
// ---------------------------------------------------------------------------

#define B_   32
#define T_   1024
#define NK_  77
#define D_   512
#define TD_  256
#define TE_  2048
#define H_   8
#define DH_  64

#define BT_ (B_ * T_)          // 32768 rows
#define BN_ (B_ * NK_)         // 2464 rows

// -------------------- scratch (static device arrays; no allocs) ------------
__device__ float g_xln[BT_ * D_];    // LN(x)
__device__ float g_q  [BT_ * D_];    // q projection
__device__ float g_y  [BT_ * D_];    // attention output
__device__ float g_h  [BT_ * D_];    // silu(modulated ln(y))
__device__ float g_xfn[BN_ * TD_];   // LN(xf)
__device__ float g_k  [BN_ * D_];    // k projection
__device__ float g_v  [BN_ * D_];    // v projection
__device__ float g_se [B_ * TE_];    // silu(emb)
__device__ float g_e  [B_ * 2 * D_]; // emb projection (scale|shift)
__device__ float g_tc [B_];          // text-cond gate

// -------------------- helpers ----------------------------------------------
__device__ __forceinline__ float warp_sum(float v) {
    #pragma unroll
    for (int o = 16; o > 0; o >>= 1) v += __shfl_xor_sync(0xffffffffu, v, o);
    return v;
}
__device__ __forceinline__ float to_tf32(float x) {
    uint32_t u;
    asm("cvt.rna.tf32.f32 %0, %1;" : "=r"(u) : "f"(x));
    return __uint_as_float(u);
}
__device__ __forceinline__ uint32_t f2tf32(float x) {
    uint32_t u;
    asm("cvt.rna.tf32.f32 %0, %1;" : "=r"(u) : "f"(x));
    return u;
}
__device__ __forceinline__ void split_tf32(float x, uint32_t& hi, uint32_t& lo) {
    hi = f2tf32(x);
    lo = f2tf32(x - __uint_as_float(hi));
}
__device__ __forceinline__ void mma_tf32(float* c, const uint32_t* a, uint32_t b0, uint32_t b1) {
    asm volatile(
        "mma.sync.aligned.m16n8k8.row.col.f32.tf32.tf32.f32 "
        "{%0,%1,%2,%3}, {%4,%5,%6,%7}, {%8,%9}, {%0,%1,%2,%3};"
        : "+f"(c[0]), "+f"(c[1]), "+f"(c[2]), "+f"(c[3])
        : "r"(a[0]), "r"(a[1]), "r"(a[2]), "r"(a[3]), "r"(b0), "r"(b1));
}

// -------------------- tiny kernels ------------------------------------------
__global__ void tc_kernel(const int* __restrict__ cond, float* __restrict__ tcv) {
    int i = threadIdx.x;
    if (i < B_) tcv[i] = ((cond[i] % 10) > 0) ? 1.0f : 0.0f;
}

__global__ void silu_kernel(const float* __restrict__ x, float* __restrict__ o, int n) {
    int i = blockIdx.x * blockDim.x + threadIdx.x;
    if (i < n) {
        float v = x[i];
        o[i] = v / (1.0f + expf(-v));
    }
}

// -------------------- LayerNorm: one warp per row ----------------------------
template <int D>
__global__ void ln_kernel(const float* __restrict__ x, const float* __restrict__ w,
                          const float* __restrict__ b, float* __restrict__ o, int rows) {
    int warpId = (blockIdx.x * blockDim.x + threadIdx.x) >> 5;
    int lane = threadIdx.x & 31;
    if (warpId >= rows) return;
    constexpr int IT = D / 128;  // float4 iterations per lane
    const float4* xr = (const float4*)(x + (size_t)warpId * D);
    float4 v[IT];
    float s = 0.f, s2 = 0.f;
    #pragma unroll
    for (int i = 0; i < IT; i++) {
        v[i] = xr[lane + i * 32];
        s  += v[i].x + v[i].y + v[i].z + v[i].w;
        s2 += v[i].x * v[i].x + v[i].y * v[i].y + v[i].z * v[i].z + v[i].w * v[i].w;
    }
    s = warp_sum(s); s2 = warp_sum(s2);
    float mu = s * (1.0f / D);
    float var = s2 * (1.0f / D) - mu * mu;
    float r = rsqrtf(var + 1e-5f);
    float4* orow = (float4*)(o + (size_t)warpId * D);
    const float4* wv = (const float4*)w;
    const float4* bv = (const float4*)b;
    #pragma unroll
    for (int i = 0; i < IT; i++) {
        int idx = lane + i * 32;
        float4 W = wv[idx], Bb = bv[idx];
        float4 u;
        u.x = (v[i].x - mu) * r * W.x + Bb.x;
        u.y = (v[i].y - mu) * r * W.y + Bb.y;
        u.z = (v[i].z - mu) * r * W.z + Bb.z;
        u.w = (v[i].w - mu) * r * W.w + Bb.w;
        orow[idx] = u;
    }
}

// -------------------- fused LN + modulation + silu ---------------------------
__global__ void modulate_kernel(const float* __restrict__ y, const float* __restrict__ w,
                                const float* __restrict__ b, const float* __restrict__ e,
                                float* __restrict__ h, int rows) {
    int warpId = (blockIdx.x * blockDim.x + threadIdx.x) >> 5;
    int lane = threadIdx.x & 31;
    if (warpId >= rows) return;
    int bIdx = warpId >> 10;  // row / T_
    const float4* yr = (const float4*)(y + (size_t)warpId * D_);
    float4 v[4];
    float s = 0.f, s2 = 0.f;
    #pragma unroll
    for (int i = 0; i < 4; i++) {
        v[i] = yr[lane + i * 32];
        s  += v[i].x + v[i].y + v[i].z + v[i].w;
        s2 += v[i].x * v[i].x + v[i].y * v[i].y + v[i].z * v[i].z + v[i].w * v[i].w;
    }
    s = warp_sum(s); s2 = warp_sum(s2);
    float mu = s * (1.0f / D_);
    float var = s2 * (1.0f / D_) - mu * mu;
    float r = rsqrtf(var + 1e-5f);
    float4* hr = (float4*)(h + (size_t)warpId * D_);
    const float4* wv = (const float4*)w;
    const float4* bv = (const float4*)b;
    const float4* sc = (const float4*)(e + (size_t)bIdx * 2 * D_);
    const float4* sh = (const float4*)(e + (size_t)bIdx * 2 * D_ + D_);
    #pragma unroll
    for (int i = 0; i < 4; i++) {
        int idx = lane + i * 32;
        float4 W = wv[idx], Bb = bv[idx], S = sc[idx], Hh = sh[idx];
        float u, val;
        float4 o;
        u = (v[i].x - mu) * r * W.x + Bb.x; val = u * (1.0f + S.x) + Hh.x; o.x = val / (1.0f + expf(-val));
        u = (v[i].y - mu) * r * W.y + Bb.y; val = u * (1.0f + S.y) + Hh.y; o.y = val / (1.0f + expf(-val));
        u = (v[i].z - mu) * r * W.z + Bb.z; val = u * (1.0f + S.z) + Hh.z; o.z = val / (1.0f + expf(-val));
        u = (v[i].w - mu) * r * W.w + Bb.w; val = u * (1.0f + S.w) + Hh.w; o.w = val / (1.0f + expf(-val));
        hr[idx] = o;
    }
}

// -------------------- tf32 MMA GEMM: C = A @ W^T + bias (+res) ---------------
// A: [M,K] row-major. W: [N,K] row-major. 128x128x32 tile, 256 threads.
// Register-prefetch over the K loop. Pinned at 2 CTAs/SM.
__global__ __launch_bounds__(256, 2) void mma_gemm_wt(
    const float* __restrict__ A, const float* __restrict__ W,
    const float* __restrict__ bias, const float* __restrict__ res,
    float* __restrict__ C, int M, int N, int K)
{
    __shared__ float As[128][36];
    __shared__ float Bs[128][36];
    const int tid  = threadIdx.x;
    const int bm   = blockIdx.y * 128;
    const int bn   = blockIdx.x * 128;
    const int warp = tid >> 5, lane = tid & 31;
    const int warpM = warp & 3;
    const int warpN = warp >> 2;
    const int g = lane >> 2;
    const int q = lane & 3;
    const int loadRow = tid >> 3;         // 0..31 (phase p adds 32p)
    const int loadK   = (tid & 7) << 2;   // 0,4,...,28

    float acc[2][8][4];
    #pragma unroll
    for (int mt = 0; mt < 2; mt++)
        #pragma unroll
        for (int nt = 0; nt < 8; nt++)
            #pragma unroll
            for (int i = 0; i < 4; i++) acc[mt][nt][i] = 0.f;

    float4 pa[4], pb[4];
    const float4 z4 = make_float4(0.f, 0.f, 0.f, 0.f);
    #pragma unroll
    for (int p = 0; p < 4; p++) {
        int row = p * 32 + loadRow;
        pa[p] = (bm + row < M)
            ? *(const float4*)(A + (size_t)(bm + row) * K + loadK) : z4;
        pb[p] = *(const float4*)(W + (size_t)(bn + row) * K + loadK);
    }

    for (int k0 = 0; k0 < K; k0 += 32) {
        // ---- stage current prefetched tile into smem (tf32-rounded) ----
        #pragma unroll
        for (int p = 0; p < 4; p++) {
            int row = p * 32 + loadRow;
            float4 a4 = pa[p], b4 = pb[p];
            a4.x = to_tf32(a4.x); a4.y = to_tf32(a4.y);
            a4.z = to_tf32(a4.z); a4.w = to_tf32(a4.w);
            b4.x = to_tf32(b4.x); b4.y = to_tf32(b4.y);
            b4.z = to_tf32(b4.z); b4.w = to_tf32(b4.w);
            *(float4*)&As[row][loadK] = a4;
            *(float4*)&Bs[row][loadK] = b4;
        }
        __syncthreads();
        // ---- prefetch next tile ----
        if (k0 + 32 < K) {
            #pragma unroll
            for (int p = 0; p < 4; p++) {
                int row = p * 32 + loadRow;
                pa[p] = (bm + row < M)
                    ? *(const float4*)(A + (size_t)(bm + row) * K + k0 + 32 + loadK) : z4;
                pb[p] = *(const float4*)(W + (size_t)(bn + row) * K + k0 + 32 + loadK);
            }
        }
        // ---- mma over 4 k-steps of 8 ----
        #pragma unroll
        for (int kk = 0; kk < 32; kk += 8) {
            uint32_t afrag[2][4];
            #pragma unroll
            for (int mt = 0; mt < 2; mt++) {
                int r0 = warpM * 32 + mt * 16 + g;
                afrag[mt][0] = __float_as_uint(As[r0][kk + q]);
                afrag[mt][1] = __float_as_uint(As[r0 + 8][kk + q]);
                afrag[mt][2] = __float_as_uint(As[r0][kk + 4 + q]);
                afrag[mt][3] = __float_as_uint(As[r0 + 8][kk + 4 + q]);
            }
            #pragma unroll
            for (int nt = 0; nt < 8; nt++) {
                int c0 = warpN * 64 + nt * 8 + g;
                uint32_t b0 = __float_as_uint(Bs[c0][kk + q]);
                uint32_t b1 = __float_as_uint(Bs[c0][kk + 4 + q]);
                mma_tf32(acc[0][nt], afrag[0], b0, b1);
                mma_tf32(acc[1][nt], afrag[1], b0, b1);
            }
        }
        __syncthreads();
    }

    // ---- epilogue: bias (+res), float2 stores ----
    #pragma unroll
    for (int mt = 0; mt < 2; mt++) {
        int row0 = bm + warpM * 32 + mt * 16 + g;
        #pragma unroll
        for (int nt = 0; nt < 8; nt++) {
            int col = bn + warpN * 64 + nt * 8 + q * 2;
            float bx = bias[col], by = bias[col + 1];
            if (row0 < M) {
                float2 o = make_float2(acc[mt][nt][0] + bx, acc[mt][nt][1] + by);
                if (res) {
                    float2 rr = *(const float2*)&res[(size_t)row0 * N + col];
                    o.x += rr.x; o.y += rr.y;
                }
                *(float2*)&C[(size_t)row0 * N + col] = o;
            }
            if (row0 + 8 < M) {
                float2 o = make_float2(acc[mt][nt][2] + bx, acc[mt][nt][3] + by);
                if (res) {
                    float2 rr = *(const float2*)&res[(size_t)(row0 + 8) * N + col];
                    o.x += rr.x; o.y += rr.y;
                }
                *(float2*)&C[(size_t)(row0 + 8) * N + col] = o;
            }
        }
    }
}

// -------------------- small GEMM: e[b,n] = silu(emb)[b,:] . emb_w[n,:] -------
__global__ void emb_gemm_kernel(const float* __restrict__ se, const float* __restrict__ W,
                                const float* __restrict__ bias, float* __restrict__ e) {
    int warpId = (blockIdx.x * blockDim.x + threadIdx.x) >> 5;
    int lane = threadIdx.x & 31;
    if (warpId >= B_ * 2 * D_) return;
    int b = warpId / (2 * D_);
    int n = warpId % (2 * D_);
    const float4* sa = (const float4*)(se + (size_t)b * TE_);
    const float4* wa = (const float4*)(W + (size_t)n * TE_);
    float s = 0.f;
    #pragma unroll
    for (int i = lane; i < TE_ / 4; i += 32) {
        float4 a = sa[i], w = wa[i];
        s += a.x * w.x + a.y * w.y + a.z * w.z + a.w * w.w;
    }
    s = warp_sum(s);
    if (lane == 0) e[(size_t)b * 2 * D_ + n] = s + bias[n];
}

// -------------------- tensor-core attention (tf32x3) — R2-exact --------------
#define QK_STRIDE 68
#define PS_STRIDE 84
#define ATTN_SMEM ((128 * QK_STRIDE + 80 * QK_STRIDE + 64 * PS_STRIDE) * 4)

__global__ __launch_bounds__(256) void attn_mma_kernel(
    const float* __restrict__ q, const float* __restrict__ k,
    const float* __restrict__ v, const float* __restrict__ tc,
    float* __restrict__ y)
{
    extern __shared__ float sm[];
    float* Qs  = sm;                                       // [128][68]
    float* Ks  = sm + 128 * QK_STRIDE;                     // [80][68]
    float* Ps  = sm;                                       // overlay of Qs/Ks
    float* Vst = sm + 128 * QK_STRIDE + 80 * QK_STRIDE;    // [64][84]

    const int b = blockIdx.x >> 3, h = blockIdx.x & 7;
    const int t0 = blockIdx.y * 128;
    const int tid = threadIdx.x;
    const int warp = tid >> 5, lane = tid & 31;
    const int g = lane >> 2, qd = lane & 3;

    const float* qbase = q + ((size_t)(b * T_ + t0)) * D_ + h * DH_;
    #pragma unroll
    for (int it = 0; it < 8; it++) {
        int idx = it * 256 + tid;
        int r = idx >> 4, j = (idx & 15) << 2;
        *(float4*)&Qs[r * QK_STRIDE + j] = *(const float4*)(qbase + (size_t)r * D_ + j);
    }
    const float* kbase = k + ((size_t)b * NK_) * D_ + h * DH_;
    #pragma unroll
    for (int it = 0; it < 5; it++) {
        int idx = it * 256 + tid;
        int r = idx >> 4, j = (idx & 15) << 2;
        float4 kv = (r < NK_) ? *(const float4*)(kbase + (size_t)r * D_ + j)
                              : make_float4(0.f, 0.f, 0.f, 0.f);
        *(float4*)&Ks[r * QK_STRIDE + j] = kv;
    }
    const float* vbase = v + ((size_t)b * NK_) * D_ + h * DH_;
    #pragma unroll
    for (int it = 0; it < 5; it++) {
        int idx = it * 256 + tid;
        int jg = idx / 80, n = idx - jg * 80;
        int j = jg << 2;
        float4 vv = (n < NK_) ? *(const float4*)(vbase + (size_t)n * D_ + j)
                              : make_float4(0.f, 0.f, 0.f, 0.f);
        Vst[(j + 0) * PS_STRIDE + n] = vv.x;
        Vst[(j + 1) * PS_STRIDE + n] = vv.y;
        Vst[(j + 2) * PS_STRIDE + n] = vv.z;
        Vst[(j + 3) * PS_STRIDE + n] = vv.w;
    }
    __syncthreads();

    float s_acc[10][4];
    #pragma unroll
    for (int nt = 0; nt < 10; nt++)
        #pragma unroll
        for (int i = 0; i < 4; i++) s_acc[nt][i] = 0.f;

    const int mrow = warp * 16;
    #pragma unroll
    for (int kk = 0; kk < DH_; kk += 8) {
        uint32_t ahi[4], alo[4];
        split_tf32(Qs[(mrow + g)     * QK_STRIDE + kk + qd],     ahi[0], alo[0]);
        split_tf32(Qs[(mrow + g + 8) * QK_STRIDE + kk + qd],     ahi[1], alo[1]);
        split_tf32(Qs[(mrow + g)     * QK_STRIDE + kk + 4 + qd], ahi[2], alo[2]);
        split_tf32(Qs[(mrow + g + 8) * QK_STRIDE + kk + 4 + qd], ahi[3], alo[3]);
        #pragma unroll
        for (int nt = 0; nt < 10; nt++) {
            uint32_t b0h, b0l, b1h, b1l;
            split_tf32(Ks[(nt * 8 + g) * QK_STRIDE + kk + qd],     b0h, b0l);
            split_tf32(Ks[(nt * 8 + g) * QK_STRIDE + kk + 4 + qd], b1h, b1l);
            mma_tf32(s_acc[nt], ahi, b0h, b1h);
            mma_tf32(s_acc[nt], ahi, b0l, b1l);
            mma_tf32(s_acc[nt], alo, b0h, b1h);
        }
    }
    __syncthreads();

    #pragma unroll
    for (int nt = 0; nt < 10; nt++)
        #pragma unroll
        for (int d2 = 0; d2 < 2; d2++) {
            int col = nt * 8 + 2 * qd + d2;
            if (col >= NK_) { s_acc[nt][d2] = -1e30f; s_acc[nt][2 + d2] = -1e30f; }
        }
    float m0 = -1e30f, m1 = -1e30f;
    #pragma unroll
    for (int nt = 0; nt < 10; nt++) {
        m0 = fmaxf(m0, fmaxf(s_acc[nt][0], s_acc[nt][1]));
        m1 = fmaxf(m1, fmaxf(s_acc[nt][2], s_acc[nt][3]));
    }
    m0 = fmaxf(m0, __shfl_xor_sync(0xffffffffu, m0, 1));
    m0 = fmaxf(m0, __shfl_xor_sync(0xffffffffu, m0, 2));
    m1 = fmaxf(m1, __shfl_xor_sync(0xffffffffu, m1, 1));
    m1 = fmaxf(m1, __shfl_xor_sync(0xffffffffu, m1, 2));
    float sum0 = 0.f, sum1 = 0.f;
    #pragma unroll
    for (int nt = 0; nt < 10; nt++) {
        s_acc[nt][0] = __expf(s_acc[nt][0] - m0); sum0 += s_acc[nt][0];
        s_acc[nt][1] = __expf(s_acc[nt][1] - m0); sum0 += s_acc[nt][1];
        s_acc[nt][2] = __expf(s_acc[nt][2] - m1); sum1 += s_acc[nt][2];
        s_acc[nt][3] = __expf(s_acc[nt][3] - m1); sum1 += s_acc[nt][3];
    }
    sum0 += __shfl_xor_sync(0xffffffffu, sum0, 1);
    sum0 += __shfl_xor_sync(0xffffffffu, sum0, 2);
    sum1 += __shfl_xor_sync(0xffffffffu, sum1, 1);
    sum1 += __shfl_xor_sync(0xffffffffu, sum1, 2);
    const float inv0 = 1.0f / sum0, inv1 = 1.0f / sum1;

    float* pw = Ps + warp * 16 * PS_STRIDE;
    #pragma unroll
    for (int nt = 0; nt < 10; nt++) {
        int col = nt * 8 + 2 * qd;
        pw[g * PS_STRIDE + col]           = s_acc[nt][0] * inv0;
        pw[g * PS_STRIDE + col + 1]       = s_acc[nt][1] * inv0;
        pw[(g + 8) * PS_STRIDE + col]     = s_acc[nt][2] * inv1;
        pw[(g + 8) * PS_STRIDE + col + 1] = s_acc[nt][3] * inv1;
    }
    __syncwarp();

    float y_acc[8][4];
    #pragma unroll
    for (int nt = 0; nt < 8; nt++)
        #pragma unroll
        for (int i = 0; i < 4; i++) y_acc[nt][i] = 0.f;

    #pragma unroll
    for (int kt = 0; kt < 10; kt++) {
        int kk = kt * 8;
        uint32_t ahi[4], alo[4];
        split_tf32(pw[g * PS_STRIDE + kk + qd],           ahi[0], alo[0]);
        split_tf32(pw[(g + 8) * PS_STRIDE + kk + qd],     ahi[1], alo[1]);
        split_tf32(pw[g * PS_STRIDE + kk + 4 + qd],       ahi[2], alo[2]);
        split_tf32(pw[(g + 8) * PS_STRIDE + kk + 4 + qd], ahi[3], alo[3]);
        #pragma unroll
        for (int nt = 0; nt < 8; nt++) {
            uint32_t b0h, b0l, b1h, b1l;
            split_tf32(Vst[(nt * 8 + g) * PS_STRIDE + kk + qd],     b0h, b0l);
            split_tf32(Vst[(nt * 8 + g) * PS_STRIDE + kk + 4 + qd], b1h, b1l);
            mma_tf32(y_acc[nt], ahi, b0h, b1h);
            mma_tf32(y_acc[nt], ahi, b0l, b1l);
            mma_tf32(y_acc[nt], alo, b0h, b1h);
        }
    }

    const float tcb = tc[b];
    const int trow = t0 + warp * 16;
    #pragma unroll
    for (int nt = 0; nt < 8; nt++) {
        int col = h * DH_ + nt * 8 + 2 * qd;
        float2 o0 = make_float2(y_acc[nt][0] * tcb, y_acc[nt][1] * tcb);
        *(float2*)&y[((size_t)(b * T_ + trow + g)) * D_ + col] = o0;
        float2 o1 = make_float2(y_acc[nt][2] * tcb, y_acc[nt][3] * tcb);
        *(float2*)&y[((size_t)(b * T_ + trow + g + 8)) * D_ + col] = o1;
    }
}

// ---------------------------------------------------------------------------
extern "C" void kernel_launch(void* const* d_in, const int* in_sizes, int n_in,
                              void* d_out, int out_size) {
    const float* x       = (const float*)d_in[0];
    const float* xf      = (const float*)d_in[1];
    const float* emb     = (const float*)d_in[2];
    // d_in[3] = src_mask (unused by reference)
    const int*   cond    = (const int*)d_in[4];
    const float* norm_w  = (const float*)d_in[5];
    const float* norm_b  = (const float*)d_in[6];
    const float* tnorm_w = (const float*)d_in[7];
    const float* tnorm_b = (const float*)d_in[8];
    const float* Wq      = (const float*)d_in[9];
    const float* bq      = (const float*)d_in[10];
    const float* Wk      = (const float*)d_in[11];
    const float* bk      = (const float*)d_in[12];
    const float* Wv      = (const float*)d_in[13];
    const float* bv      = (const float*)d_in[14];
    const float* emb_w   = (const float*)d_in[15];
    const float* emb_b   = (const float*)d_in[16];
    const float* snorm_w = (const float*)d_in[17];
    const float* snorm_b = (const float*)d_in[18];
    const float* Wout    = (const float*)d_in[19];
    const float* bout    = (const float*)d_in[20];
    float* out = (float*)d_out;

    float *p_xln, *p_q, *p_y, *p_h, *p_xfn, *p_k, *p_v, *p_se, *p_e, *p_tc;
    cudaGetSymbolAddress((void**)&p_xln, g_xln);
    cudaGetSymbolAddress((void**)&p_q,   g_q);
    cudaGetSymbolAddress((void**)&p_y,   g_y);
    cudaGetSymbolAddress((void**)&p_h,   g_h);
    cudaGetSymbolAddress((void**)&p_xfn, g_xfn);
    cudaGetSymbolAddress((void**)&p_k,   g_k);
    cudaGetSymbolAddress((void**)&p_v,   g_v);
    cudaGetSymbolAddress((void**)&p_se,  g_se);
    cudaGetSymbolAddress((void**)&p_e,   g_e);
    cudaGetSymbolAddress((void**)&p_tc,  g_tc);

    static bool attr_set = false;
    if (!attr_set) {
        cudaFuncSetAttribute(attn_mma_kernel,
                             cudaFuncAttributeMaxDynamicSharedMemorySize, ATTN_SMEM);
        attr_set = true;
    }

    // gates + silu(emb)
    tc_kernel<<<1, 32>>>(cond, p_tc);
    silu_kernel<<<(B_ * TE_ + 255) / 256, 256>>>(emb, p_se, B_ * TE_);

    // LayerNorms (warp per row)
    ln_kernel<D_><<<(BT_ * 32 + 255) / 256, 256>>>(x, norm_w, norm_b, p_xln, BT_);
    ln_kernel<TD_><<<(BN_ * 32 + 255) / 256, 256>>>(xf, tnorm_w, tnorm_b, p_xfn, BN_);

    // projections (tf32 tensor cores)
    {
        dim3 grid(D_ / 128, (BT_ + 127) / 128);
        mma_gemm_wt<<<grid, 256>>>(p_xln, Wq, bq, nullptr, p_q, BT_, D_, D_);
    }
    {
        dim3 grid(D_ / 128, (BN_ + 127) / 128);
        mma_gemm_wt<<<grid, 256>>>(p_xfn, Wk, bk, nullptr, p_k, BN_, D_, TD_);
        mma_gemm_wt<<<grid, 256>>>(p_xfn, Wv, bv, nullptr, p_v, BN_, D_, TD_);
    }

    // emb MLP: e = silu(emb) @ emb_w^T + emb_b
    emb_gemm_kernel<<<(B_ * 2 * D_ * 32 + 255) / 256, 256>>>(p_se, emb_w, emb_b, p_e);

    // attention (tensor-core, tf32x3; bias dropped: softmax shift-invariant)
    {
        dim3 grid(B_ * H_, T_ / 128);
        attn_mma_kernel<<<grid, 256, ATTN_SMEM>>>(p_q, p_k, p_v, p_tc, p_y);
    }

    // modulation: h = silu(ln(y) * (1+scale) + shift)
    modulate_kernel<<<(BT_ * 32 + 255) / 256, 256>>>(p_y, snorm_w, snorm_b, p_e, p_h, BT_);

    // out = x + h @ Wout^T + bout  (residual fused into epilogue)
    {
        dim3 grid(D_ / 128, (BT_ + 127) / 128);
        mma_gemm_wt<<<grid, 256>>>(p_h, Wout, bout, x, out, BT_, D_, D_);
    }
}

// round 14
// speedup vs baseline: 1.0036x; 1.0036x over previous
#include <cuda_runtime.h>
#include <cuda_bf16.h>
#include <math.h>
#include <stdint.h>

// ---------------------------------------------------------------------------
// BaseCrossAttention fused pipeline.
// R2-exact structure (proven 495.6us) + __launch_bounds__(256,2) on the GEMM
// to pin 2 CTAs/SM (occupancy hypothesis test).
// B=32, T=1024, N=77, D=512, TD=256, TE=2048, H=8, dh=64
// ---------------------------------------------------------------------------

#define B_   32
#define T_   1024
#define NK_  77
#define D_   512
#define TD_  256
#define TE_  2048
#define H_   8
#define DH_  64

#define BT_ (B_ * T_)          // 32768 rows
#define BN_ (B_ * NK_)         // 2464 rows

// -------------------- scratch (static device arrays; no allocs) ------------
__device__ float g_xln[BT_ * D_];    // LN(x)
__device__ float g_q  [BT_ * D_];    // q projection
__device__ float g_y  [BT_ * D_];    // attention output
__device__ float g_h  [BT_ * D_];    // silu(modulated ln(y))
__device__ float g_xfn[BN_ * TD_];   // LN(xf)
__device__ float g_k  [BN_ * D_];    // k projection
__device__ float g_v  [BN_ * D_];    // v projection
__device__ float g_se [B_ * TE_];    // silu(emb)
__device__ float g_e  [B_ * 2 * D_]; // emb projection (scale|shift)
__device__ float g_tc [B_];          // text-cond gate

// -------------------- helpers ----------------------------------------------
__device__ __forceinline__ float warp_sum(float v) {
    #pragma unroll
    for (int o = 16; o > 0; o >>= 1) v += __shfl_xor_sync(0xffffffffu, v, o);
    return v;
}
__device__ __forceinline__ float to_tf32(float x) {
    uint32_t u;
    asm("cvt.rna.tf32.f32 %0, %1;" : "=r"(u) : "f"(x));
    return __uint_as_float(u);
}
__device__ __forceinline__ uint32_t f2tf32(float x) {
    uint32_t u;
    asm("cvt.rna.tf32.f32 %0, %1;" : "=r"(u) : "f"(x));
    return u;
}
__device__ __forceinline__ void split_tf32(float x, uint32_t& hi, uint32_t& lo) {
    hi = f2tf32(x);
    lo = f2tf32(x - __uint_as_float(hi));
}
__device__ __forceinline__ void mma_tf32(float* c, const uint32_t* a, uint32_t b0, uint32_t b1) {
    asm volatile(
        "mma.sync.aligned.m16n8k8.row.col.f32.tf32.tf32.f32 "
        "{%0,%1,%2,%3}, {%4,%5,%6,%7}, {%8,%9}, {%0,%1,%2,%3};"
        : "+f"(c[0]), "+f"(c[1]), "+f"(c[2]), "+f"(c[3])
        : "r"(a[0]), "r"(a[1]), "r"(a[2]), "r"(a[3]), "r"(b0), "r"(b1));
}

// -------------------- tiny kernels ------------------------------------------
__global__ void tc_kernel(const int* __restrict__ cond, float* __restrict__ tcv) {
    int i = threadIdx.x;
    if (i < B_) tcv[i] = ((cond[i] % 10) > 0) ? 1.0f : 0.0f;
}

__global__ void silu_kernel(const float* __restrict__ x, float* __restrict__ o, int n) {
    int i = blockIdx.x * blockDim.x + threadIdx.x;
    if (i < n) {
        float v = x[i];
        o[i] = v / (1.0f + expf(-v));
    }
}

// -------------------- LayerNorm: one warp per row ----------------------------
template <int D>
__global__ void ln_kernel(const float* __restrict__ x, const float* __restrict__ w,
                          const float* __restrict__ b, float* __restrict__ o, int rows) {
    int warpId = (blockIdx.x * blockDim.x + threadIdx.x) >> 5;
    int lane = threadIdx.x & 31;
    if (warpId >= rows) return;
    constexpr int IT = D / 128;  // float4 iterations per lane
    const float4* xr = (const float4*)(x + (size_t)warpId * D);
    float4 v[IT];
    float s = 0.f, s2 = 0.f;
    #pragma unroll
    for (int i = 0; i < IT; i++) {
        v[i] = xr[lane + i * 32];
        s  += v[i].x + v[i].y + v[i].z + v[i].w;
        s2 += v[i].x * v[i].x + v[i].y * v[i].y + v[i].z * v[i].z + v[i].w * v[i].w;
    }
    s = warp_sum(s); s2 = warp_sum(s2);
    float mu = s * (1.0f / D);
    float var = s2 * (1.0f / D) - mu * mu;
    float r = rsqrtf(var + 1e-5f);
    float4* orow = (float4*)(o + (size_t)warpId * D);
    const float4* wv = (const float4*)w;
    const float4* bv = (const float4*)b;
    #pragma unroll
    for (int i = 0; i < IT; i++) {
        int idx = lane + i * 32;
        float4 W = wv[idx], Bb = bv[idx];
        float4 u;
        u.x = (v[i].x - mu) * r * W.x + Bb.x;
        u.y = (v[i].y - mu) * r * W.y + Bb.y;
        u.z = (v[i].z - mu) * r * W.z + Bb.z;
        u.w = (v[i].w - mu) * r * W.w + Bb.w;
        orow[idx] = u;
    }
}

// -------------------- fused LN + modulation + silu ---------------------------
__global__ void modulate_kernel(const float* __restrict__ y, const float* __restrict__ w,
                                const float* __restrict__ b, const float* __restrict__ e,
                                float* __restrict__ h, int rows) {
    int warpId = (blockIdx.x * blockDim.x + threadIdx.x) >> 5;
    int lane = threadIdx.x & 31;
    if (warpId >= rows) return;
    int bIdx = warpId >> 10;  // row / T_
    const float4* yr = (const float4*)(y + (size_t)warpId * D_);
    float4 v[4];
    float s = 0.f, s2 = 0.f;
    #pragma unroll
    for (int i = 0; i < 4; i++) {
        v[i] = yr[lane + i * 32];
        s  += v[i].x + v[i].y + v[i].z + v[i].w;
        s2 += v[i].x * v[i].x + v[i].y * v[i].y + v[i].z * v[i].z + v[i].w * v[i].w;
    }
    s = warp_sum(s); s2 = warp_sum(s2);
    float mu = s * (1.0f / D_);
    float var = s2 * (1.0f / D_) - mu * mu;
    float r = rsqrtf(var + 1e-5f);
    float4* hr = (float4*)(h + (size_t)warpId * D_);
    const float4* wv = (const float4*)w;
    const float4* bv = (const float4*)b;
    const float4* sc = (const float4*)(e + (size_t)bIdx * 2 * D_);
    const float4* sh = (const float4*)(e + (size_t)bIdx * 2 * D_ + D_);
    #pragma unroll
    for (int i = 0; i < 4; i++) {
        int idx = lane + i * 32;
        float4 W = wv[idx], Bb = bv[idx], S = sc[idx], Hh = sh[idx];
        float u, val;
        float4 o;
        u = (v[i].x - mu) * r * W.x + Bb.x; val = u * (1.0f + S.x) + Hh.x; o.x = val / (1.0f + expf(-val));
        u = (v[i].y - mu) * r * W.y + Bb.y; val = u * (1.0f + S.y) + Hh.y; o.y = val / (1.0f + expf(-val));
        u = (v[i].z - mu) * r * W.z + Bb.z; val = u * (1.0f + S.z) + Hh.z; o.z = val / (1.0f + expf(-val));
        u = (v[i].w - mu) * r * W.w + Bb.w; val = u * (1.0f + S.w) + Hh.w; o.w = val / (1.0f + expf(-val));
        hr[idx] = o;
    }
}

// -------------------- tf32 MMA GEMM: C = A @ W^T + bias (+res) ---------------
// A: [M,K] row-major. W: [N,K] row-major. 128x128x32 tile, 256 threads.
// Register-prefetch over the K loop. Pinned at 2 CTAs/SM.
__global__ __launch_bounds__(256, 2) void mma_gemm_wt(
    const float* __restrict__ A, const float* __restrict__ W,
    const float* __restrict__ bias, const float* __restrict__ res,
    float* __restrict__ C, int M, int N, int K)
{
    __shared__ float As[128][36];
    __shared__ float Bs[128][36];
    const int tid  = threadIdx.x;
    const int bm   = blockIdx.y * 128;
    const int bn   = blockIdx.x * 128;
    const int warp = tid >> 5, lane = tid & 31;
    const int warpM = warp & 3;
    const int warpN = warp >> 2;
    const int g = lane >> 2;
    const int q = lane & 3;
    const int loadRow = tid >> 3;         // 0..31 (phase p adds 32p)
    const int loadK   = (tid & 7) << 2;   // 0,4,...,28

    float acc[2][8][4];
    #pragma unroll
    for (int mt = 0; mt < 2; mt++)
        #pragma unroll
        for (int nt = 0; nt < 8; nt++)
            #pragma unroll
            for (int i = 0; i < 4; i++) acc[mt][nt][i] = 0.f;

    float4 pa[4], pb[4];
    const float4 z4 = make_float4(0.f, 0.f, 0.f, 0.f);
    #pragma unroll
    for (int p = 0; p < 4; p++) {
        int row = p * 32 + loadRow;
        pa[p] = (bm + row < M)
            ? *(const float4*)(A + (size_t)(bm + row) * K + loadK) : z4;
        pb[p] = *(const float4*)(W + (size_t)(bn + row) * K + loadK);
    }

    for (int k0 = 0; k0 < K; k0 += 32) {
        // ---- stage current prefetched tile into smem (tf32-rounded) ----
        #pragma unroll
        for (int p = 0; p < 4; p++) {
            int row = p * 32 + loadRow;
            float4 a4 = pa[p], b4 = pb[p];
            a4.x = to_tf32(a4.x); a4.y = to_tf32(a4.y);
            a4.z = to_tf32(a4.z); a4.w = to_tf32(a4.w);
            b4.x = to_tf32(b4.x); b4.y = to_tf32(b4.y);
            b4.z = to_tf32(b4.z); b4.w = to_tf32(b4.w);
            *(float4*)&As[row][loadK] = a4;
            *(float4*)&Bs[row][loadK] = b4;
        }
        __syncthreads();
        // ---- prefetch next tile ----
        if (k0 + 32 < K) {
            #pragma unroll
            for (int p = 0; p < 4; p++) {
                int row = p * 32 + loadRow;
                pa[p] = (bm + row < M)
                    ? *(const float4*)(A + (size_t)(bm + row) * K + k0 + 32 + loadK) : z4;
                pb[p] = *(const float4*)(W + (size_t)(bn + row) * K + k0 + 32 + loadK);
            }
        }
        // ---- mma over 4 k-steps of 8 ----
        #pragma unroll
        for (int kk = 0; kk < 32; kk += 8) {
            uint32_t afrag[2][4];
            #pragma unroll
            for (int mt = 0; mt < 2; mt++) {
                int r0 = warpM * 32 + mt * 16 + g;
                afrag[mt][0] = __float_as_uint(As[r0][kk + q]);
                afrag[mt][1] = __float_as_uint(As[r0 + 8][kk + q]);
                afrag[mt][2] = __float_as_uint(As[r0][kk + 4 + q]);
                afrag[mt][3] = __float_as_uint(As[r0 + 8][kk + 4 + q]);
            }
            #pragma unroll
            for (int nt = 0; nt < 8; nt++) {
                int c0 = warpN * 64 + nt * 8 + g;
                uint32_t b0 = __float_as_uint(Bs[c0][kk + q]);
                uint32_t b1 = __float_as_uint(Bs[c0][kk + 4 + q]);
                mma_tf32(acc[0][nt], afrag[0], b0, b1);
                mma_tf32(acc[1][nt], afrag[1], b0, b1);
            }
        }
        __syncthreads();
    }

    // ---- epilogue: bias (+res), float2 stores ----
    #pragma unroll
    for (int mt = 0; mt < 2; mt++) {
        int row0 = bm + warpM * 32 + mt * 16 + g;
        #pragma unroll
        for (int nt = 0; nt < 8; nt++) {
            int col = bn + warpN * 64 + nt * 8 + q * 2;
            float bx = bias[col], by = bias[col + 1];
            if (row0 < M) {
                float2 o = make_float2(acc[mt][nt][0] + bx, acc[mt][nt][1] + by);
                if (res) {
                    float2 rr = *(const float2*)&res[(size_t)row0 * N + col];
                    o.x += rr.x; o.y += rr.y;
                }
                *(float2*)&C[(size_t)row0 * N + col] = o;
            }
            if (row0 + 8 < M) {
                float2 o = make_float2(acc[mt][nt][2] + bx, acc[mt][nt][3] + by);
                if (res) {
                    float2 rr = *(const float2*)&res[(size_t)(row0 + 8) * N + col];
                    o.x += rr.x; o.y += rr.y;
                }
                *(float2*)&C[(size_t)(row0 + 8) * N + col] = o;
            }
        }
    }
}

// -------------------- small GEMM: e[b,n] = silu(emb)[b,:] . emb_w[n,:] -------
__global__ void emb_gemm_kernel(const float* __restrict__ se, const float* __restrict__ W,
                                const float* __restrict__ bias, float* __restrict__ e) {
    int warpId = (blockIdx.x * blockDim.x + threadIdx.x) >> 5;
    int lane = threadIdx.x & 31;
    if (warpId >= B_ * 2 * D_) return;
    int b = warpId / (2 * D_);
    int n = warpId % (2 * D_);
    const float4* sa = (const float4*)(se + (size_t)b * TE_);
    const float4* wa = (const float4*)(W + (size_t)n * TE_);
    float s = 0.f;
    #pragma unroll
    for (int i = lane; i < TE_ / 4; i += 32) {
        float4 a = sa[i], w = wa[i];
        s += a.x * w.x + a.y * w.y + a.z * w.z + a.w * w.w;
    }
    s = warp_sum(s);
    if (lane == 0) e[(size_t)b * 2 * D_ + n] = s + bias[n];
}

// -------------------- tensor-core attention (tf32x3) — R2-exact --------------
#define QK_STRIDE 68
#define PS_STRIDE 84
#define ATTN_SMEM ((128 * QK_STRIDE + 80 * QK_STRIDE + 64 * PS_STRIDE) * 4)

__global__ __launch_bounds__(256) void attn_mma_kernel(
    const float* __restrict__ q, const float* __restrict__ k,
    const float* __restrict__ v, const float* __restrict__ tc,
    float* __restrict__ y)
{
    extern __shared__ float sm[];
    float* Qs  = sm;                                       // [128][68]
    float* Ks  = sm + 128 * QK_STRIDE;                     // [80][68]
    float* Ps  = sm;                                       // overlay of Qs/Ks
    float* Vst = sm + 128 * QK_STRIDE + 80 * QK_STRIDE;    // [64][84]

    const int b = blockIdx.x >> 3, h = blockIdx.x & 7;
    const int t0 = blockIdx.y * 128;
    const int tid = threadIdx.x;
    const int warp = tid >> 5, lane = tid & 31;
    const int g = lane >> 2, qd = lane & 3;

    const float* qbase = q + ((size_t)(b * T_ + t0)) * D_ + h * DH_;
    #pragma unroll
    for (int it = 0; it < 8; it++) {
        int idx = it * 256 + tid;
        int r = idx >> 4, j = (idx & 15) << 2;
        *(float4*)&Qs[r * QK_STRIDE + j] = *(const float4*)(qbase + (size_t)r * D_ + j);
    }
    const float* kbase = k + ((size_t)b * NK_) * D_ + h * DH_;
    #pragma unroll
    for (int it = 0; it < 5; it++) {
        int idx = it * 256 + tid;
        int r = idx >> 4, j = (idx & 15) << 2;
        float4 kv = (r < NK_) ? *(const float4*)(kbase + (size_t)r * D_ + j)
                              : make_float4(0.f, 0.f, 0.f, 0.f);
        *(float4*)&Ks[r * QK_STRIDE + j] = kv;
    }
    const float* vbase = v + ((size_t)b * NK_) * D_ + h * DH_;
    #pragma unroll
    for (int it = 0; it < 5; it++) {
        int idx = it * 256 + tid;
        int jg = idx / 80, n = idx - jg * 80;
        int j = jg << 2;
        float4 vv = (n < NK_) ? *(const float4*)(vbase + (size_t)n * D_ + j)
                              : make_float4(0.f, 0.f, 0.f, 0.f);
        Vst[(j + 0) * PS_STRIDE + n] = vv.x;
        Vst[(j + 1) * PS_STRIDE + n] = vv.y;
        Vst[(j + 2) * PS_STRIDE + n] = vv.z;
        Vst[(j + 3) * PS_STRIDE + n] = vv.w;
    }
    __syncthreads();

    float s_acc[10][4];
    #pragma unroll
    for (int nt = 0; nt < 10; nt++)
        #pragma unroll
        for (int i = 0; i < 4; i++) s_acc[nt][i] = 0.f;

    const int mrow = warp * 16;
    #pragma unroll
    for (int kk = 0; kk < DH_; kk += 8) {
        uint32_t ahi[4], alo[4];
        split_tf32(Qs[(mrow + g)     * QK_STRIDE + kk + qd],     ahi[0], alo[0]);
        split_tf32(Qs[(mrow + g + 8) * QK_STRIDE + kk + qd],     ahi[1], alo[1]);
        split_tf32(Qs[(mrow + g)     * QK_STRIDE + kk + 4 + qd], ahi[2], alo[2]);
        split_tf32(Qs[(mrow + g + 8) * QK_STRIDE + kk + 4 + qd], ahi[3], alo[3]);
        #pragma unroll
        for (int nt = 0; nt < 10; nt++) {
            uint32_t b0h, b0l, b1h, b1l;
            split_tf32(Ks[(nt * 8 + g) * QK_STRIDE + kk + qd],     b0h, b0l);
            split_tf32(Ks[(nt * 8 + g) * QK_STRIDE + kk + 4 + qd], b1h, b1l);
            mma_tf32(s_acc[nt], ahi, b0h, b1h);
            mma_tf32(s_acc[nt], ahi, b0l, b1l);
            mma_tf32(s_acc[nt], alo, b0h, b1h);
        }
    }
    __syncthreads();

    #pragma unroll
    for (int nt = 0; nt < 10; nt++)
        #pragma unroll
        for (int d2 = 0; d2 < 2; d2++) {
            int col = nt * 8 + 2 * qd + d2;
            if (col >= NK_) { s_acc[nt][d2] = -1e30f; s_acc[nt][2 + d2] = -1e30f; }
        }
    float m0 = -1e30f, m1 = -1e30f;
    #pragma unroll
    for (int nt = 0; nt < 10; nt++) {
        m0 = fmaxf(m0, fmaxf(s_acc[nt][0], s_acc[nt][1]));
        m1 = fmaxf(m1, fmaxf(s_acc[nt][2], s_acc[nt][3]));
    }
    m0 = fmaxf(m0, __shfl_xor_sync(0xffffffffu, m0, 1));
    m0 = fmaxf(m0, __shfl_xor_sync(0xffffffffu, m0, 2));
    m1 = fmaxf(m1, __shfl_xor_sync(0xffffffffu, m1, 1));
    m1 = fmaxf(m1, __shfl_xor_sync(0xffffffffu, m1, 2));
    float sum0 = 0.f, sum1 = 0.f;
    #pragma unroll
    for (int nt = 0; nt < 10; nt++) {
        s_acc[nt][0] = __expf(s_acc[nt][0] - m0); sum0 += s_acc[nt][0];
        s_acc[nt][1] = __expf(s_acc[nt][1] - m0); sum0 += s_acc[nt][1];
        s_acc[nt][2] = __expf(s_acc[nt][2] - m1); sum1 += s_acc[nt][2];
        s_acc[nt][3] = __expf(s_acc[nt][3] - m1); sum1 += s_acc[nt][3];
    }
    sum0 += __shfl_xor_sync(0xffffffffu, sum0, 1);
    sum0 += __shfl_xor_sync(0xffffffffu, sum0, 2);
    sum1 += __shfl_xor_sync(0xffffffffu, sum1, 1);
    sum1 += __shfl_xor_sync(0xffffffffu, sum1, 2);
    const float inv0 = 1.0f / sum0, inv1 = 1.0f / sum1;

    float* pw = Ps + warp * 16 * PS_STRIDE;
    #pragma unroll
    for (int nt = 0; nt < 10; nt++) {
        int col = nt * 8 + 2 * qd;
        pw[g * PS_STRIDE + col]           = s_acc[nt][0] * inv0;
        pw[g * PS_STRIDE + col + 1]       = s_acc[nt][1] * inv0;
        pw[(g + 8) * PS_STRIDE + col]     = s_acc[nt][2] * inv1;
        pw[(g + 8) * PS_STRIDE + col + 1] = s_acc[nt][3] * inv1;
    }
    __syncwarp();

    float y_acc[8][4];
    #pragma unroll
    for (int nt = 0; nt < 8; nt++)
        #pragma unroll
        for (int i = 0; i < 4; i++) y_acc[nt][i] = 0.f;

    #pragma unroll
    for (int kt = 0; kt < 10; kt++) {
        int kk = kt * 8;
        uint32_t ahi[4], alo[4];
        split_tf32(pw[g * PS_STRIDE + kk + qd],           ahi[0], alo[0]);
        split_tf32(pw[(g + 8) * PS_STRIDE + kk + qd],     ahi[1], alo[1]);
        split_tf32(pw[g * PS_STRIDE + kk + 4 + qd],       ahi[2], alo[2]);
        split_tf32(pw[(g + 8) * PS_STRIDE + kk + 4 + qd], ahi[3], alo[3]);
        #pragma unroll
        for (int nt = 0; nt < 8; nt++) {
            uint32_t b0h, b0l, b1h, b1l;
            split_tf32(Vst[(nt * 8 + g) * PS_STRIDE + kk + qd],     b0h, b0l);
            split_tf32(Vst[(nt * 8 + g) * PS_STRIDE + kk + 4 + qd], b1h, b1l);
            mma_tf32(y_acc[nt], ahi, b0h, b1h);
            mma_tf32(y_acc[nt], ahi, b0l, b1l);
            mma_tf32(y_acc[nt], alo, b0h, b1h);
        }
    }

    const float tcb = tc[b];
    const int trow = t0 + warp * 16;
    #pragma unroll
    for (int nt = 0; nt < 8; nt++) {
        int col = h * DH_ + nt * 8 + 2 * qd;
        float2 o0 = make_float2(y_acc[nt][0] * tcb, y_acc[nt][1] * tcb);
        *(float2*)&y[((size_t)(b * T_ + trow + g)) * D_ + col] = o0;
        float2 o1 = make_float2(y_acc[nt][2] * tcb, y_acc[nt][3] * tcb);
        *(float2*)&y[((size_t)(b * T_ + trow + g + 8)) * D_ + col] = o1;
    }
}

// ---------------------------------------------------------------------------
extern "C" void kernel_launch(void* const* d_in, const int* in_sizes, int n_in,
                              void* d_out, int out_size) {
    const float* x       = (const float*)d_in[0];
    const float* xf      = (const float*)d_in[1];
    const float* emb     = (const float*)d_in[2];
    // d_in[3] = src_mask (unused by reference)
    const int*   cond    = (const int*)d_in[4];
    const float* norm_w  = (const float*)d_in[5];
    const float* norm_b  = (const float*)d_in[6];
    const float* tnorm_w = (const float*)d_in[7];
    const float* tnorm_b = (const float*)d_in[8];
    const float* Wq      = (const float*)d_in[9];
    const float* bq      = (const float*)d_in[10];
    const float* Wk      = (const float*)d_in[11];
    const float* bk      = (const float*)d_in[12];
    const float* Wv      = (const float*)d_in[13];
    const float* bv      = (const float*)d_in[14];
    const float* emb_w   = (const float*)d_in[15];
    const float* emb_b   = (const float*)d_in[16];
    const float* snorm_w = (const float*)d_in[17];
    const float* snorm_b = (const float*)d_in[18];
    const float* Wout    = (const float*)d_in[19];
    const float* bout    = (const float*)d_in[20];
    float* out = (float*)d_out;

    float *p_xln, *p_q, *p_y, *p_h, *p_xfn, *p_k, *p_v, *p_se, *p_e, *p_tc;
    cudaGetSymbolAddress((void**)&p_xln, g_xln);
    cudaGetSymbolAddress((void**)&p_q,   g_q);
    cudaGetSymbolAddress((void**)&p_y,   g_y);
    cudaGetSymbolAddress((void**)&p_h,   g_h);
    cudaGetSymbolAddress((void**)&p_xfn, g_xfn);
    cudaGetSymbolAddress((void**)&p_k,   g_k);
    cudaGetSymbolAddress((void**)&p_v,   g_v);
    cudaGetSymbolAddress((void**)&p_se,  g_se);
    cudaGetSymbolAddress((void**)&p_e,   g_e);
    cudaGetSymbolAddress((void**)&p_tc,  g_tc);

    static bool attr_set = false;
    if (!attr_set) {
        cudaFuncSetAttribute(attn_mma_kernel,
                             cudaFuncAttributeMaxDynamicSharedMemorySize, ATTN_SMEM);
        attr_set = true;
    }

    // gates + silu(emb)
    tc_kernel<<<1, 32>>>(cond, p_tc);
    silu_kernel<<<(B_ * TE_ + 255) / 256, 256>>>(emb, p_se, B_ * TE_);

    // LayerNorms (warp per row)
    ln_kernel<D_><<<(BT_ * 32 + 255) / 256, 256>>>(x, norm_w, norm_b, p_xln, BT_);
    ln_kernel<TD_><<<(BN_ * 32 + 255) / 256, 256>>>(xf, tnorm_w, tnorm_b, p_xfn, BN_);

    // projections (tf32 tensor cores)
    {
        dim3 grid(D_ / 128, (BT_ + 127) / 128);
        mma_gemm_wt<<<grid, 256>>>(p_xln, Wq, bq, nullptr, p_q, BT_, D_, D_);
    }
    {
        dim3 grid(D_ / 128, (BN_ + 127) / 128);
        mma_gemm_wt<<<grid, 256>>>(p_xfn, Wk, bk, nullptr, p_k, BN_, D_, TD_);
        mma_gemm_wt<<<grid, 256>>>(p_xfn, Wv, bv, nullptr, p_v, BN_, D_, TD_);
    }

    // emb MLP: e = silu(emb) @ emb_w^T + emb_b
    emb_gemm_kernel<<<(B_ * 2 * D_ * 32 + 255) / 256, 256>>>(p_se, emb_w, emb_b, p_e);

    // attention (tensor-core, tf32x3; bias dropped: softmax shift-invariant)
    {
        dim3 grid(B_ * H_, T_ / 128);
        attn_mma_kernel<<<grid, 256, ATTN_SMEM>>>(p_q, p_k, p_v, p_tc, p_y);
    }

    // modulation: h = silu(ln(y) * (1+scale) + shift)
    modulate_kernel<<<(BT_ * 32 + 255) / 256, 256>>>(p_y, snorm_w, snorm_b, p_e, p_h, BT_);

    // out = x + h @ Wout^T + bout  (residual fused into epilogue)
    {
        dim3 grid(D_ / 128, (BT_ + 127) / 128);
        mma_gemm_wt<<<grid, 256>>>(p_h, Wout, bout, x, out, BT_, D_, D_);
    }
}